// round 3
// baseline (speedup 1.0000x reference)
#include <cuda_runtime.h>
#include <cstdint>

// B=256 batches, N=256. Greedy masked argmax assignment, one warp per batch,
// warp-synchronous. Per lane: 8 owned rows (row = j*32+lane), each with a
// head (current argmax over unmasked cols) and a backup (2nd best, eagerly
// invalidated when its col is masked). Keys are fp32 bit patterns (softmax
// values are strictly positive => order-monotone as uint32; 0 = dead/invalid).
// Selection: REDUX max over head keys, then REDUX min over packed
// (row<<8 | col) among attainers => exact reference tie-breaking
// (max value, then smallest flat index).

#define NN 256
#define FULL 0xFFFFFFFFu

__global__ __launch_bounds__(32)
void greedy_perm_kernel(const float* __restrict__ scores,
                        float* __restrict__ out) {
    __shared__ int s_perm[NN];

    const int b = blockIdx.x;
    const int lane = threadIdx.x;
    const float* base = scores + (size_t)b * NN * NN;
    float* obase = out + (size_t)b * NN * NN;

    unsigned hkey[8]; int hcol[8];
    unsigned bkey[8]; int bcol[8];
    unsigned cmask[8];
    #pragma unroll
    for (int k = 0; k < 8; k++) cmask[k] = 0u;

    // ---------- init: per-row top-2, float4 loads, 4 rows batched for MLP ----------
    #pragma unroll 1
    for (int j = 0; j < 8; j++) {
        #pragma unroll 1
        for (int rr4 = 0; rr4 < 32; rr4 += 4) {
            float4 A[4], Bv[4];
            #pragma unroll
            for (int q = 0; q < 4; q++) {
                const float4* rp = (const float4*)(base + (size_t)(j * 32 + rr4 + q) * NN);
                A[q]  = __ldg(rp + lane);
                Bv[q] = __ldg(rp + 32 + lane);
            }
            #pragma unroll
            for (int q = 0; q < 4; q++) {
                unsigned k1 = 0, k2 = 0; int c1 = 0, c2 = 0;
                float v[8] = {A[q].x, A[q].y, A[q].z, A[q].w,
                              Bv[q].x, Bv[q].y, Bv[q].z, Bv[q].w};
                #pragma unroll
                for (int i = 0; i < 8; i++) {
                    int col = (i < 4) ? (4 * lane + i) : (128 + 4 * lane + (i - 4));
                    unsigned key = __float_as_uint(v[i]);
                    if (key > k1)      { k2 = k1; c2 = c1; k1 = key; c1 = col; }
                    else if (key > k2) { k2 = key; c2 = col; }
                }
                unsigned m1 = __reduce_max_sync(FULL, k1);
                unsigned p1 = __reduce_min_sync(FULL, (k1 == m1) ? (unsigned)c1 : FULL);
                bool winner = (k1 == m1) && ((unsigned)c1 == p1);
                unsigned sk = winner ? k2 : k1;
                int      sc = winner ? c2 : c1;
                unsigned m2 = __reduce_max_sync(FULL, sk);
                unsigned p2 = __reduce_min_sync(FULL, (sk == m2) ? (unsigned)sc : FULL);
                if (lane == rr4 + q) {
                    hkey[j] = m1; hcol[j] = (int)p1;
                    bkey[j] = m2; bcol[j] = (int)p2;
                }
            }
        }
    }

    // ---------- 256 sequential greedy steps ----------
    #pragma unroll 1
    for (int it = 0; it < NN; it++) {
        // local best over 8 owned rows (ascending j + strict > => smallest row on ties)
        unsigned bk = 0, bp = 0;
        #pragma unroll
        for (int j = 0; j < 8; j++) {
            if (hkey[j] > bk) {
                bk = hkey[j];
                bp = (unsigned)(((j * 32 + lane) << 8) | hcol[j]);
            }
        }
        unsigned m = __reduce_max_sync(FULL, bk);
        unsigned sel = __reduce_min_sync(FULL, (bk == m) ? bp : FULL);
        int r = (int)(sel >> 8);
        int c = (int)(sel & 255u);

        if (lane == 0) s_perm[r] = c;

        // mask col c (replicated)
        {
            int w = c >> 5; unsigned bit = 1u << (c & 31);
            #pragma unroll
            for (int k = 0; k < 8; k++) if (k == w) cmask[k] |= bit;
        }
        // kill selected row's head
        if (lane == (r & 31)) {
            int slot = r >> 5;
            #pragma unroll
            for (int j = 0; j < 8; j++) if (j == slot) hkey[j] = 0u;
        }

        if (it == NN - 1) break;

        // pops: promote backup if head's col masked; invalidate backups hit by c
        unsigned exh = 0u;
        #pragma unroll
        for (int j = 0; j < 8; j++) {
            bool alive   = (hkey[j] != 0u);
            bool headhit = alive && (hcol[j] == c);
            bool backhit = (bcol[j] == c);
            if (headhit) {
                if (bkey[j] != 0u) { hkey[j] = bkey[j]; hcol[j] = bcol[j]; bkey[j] = 0u; }
                else               { exh |= 1u << j; }
            } else if (backhit) {
                bkey[j] = 0u;
            }
        }

        // rare: cooperative full rescan (masked top-2) for exhausted rows
        unsigned bal = __ballot_sync(FULL, exh != 0u);
        while (bal) {
            int src = __ffs(bal) - 1; bal &= bal - 1;
            unsigned em = __shfl_sync(FULL, exh, src);
            while (em) {
                int j2 = __ffs(em) - 1; em &= em - 1;
                int row = j2 * 32 + src;
                const float* rp = base + (size_t)row * NN;
                unsigned k1 = 0, k2 = 0; int c1 = 0, c2 = 0;
                #pragma unroll
                for (int k = 0; k < 8; k++) {
                    int col = k * 32 + lane;
                    float v = __ldg(rp + col);
                    unsigned key = ((cmask[k] >> lane) & 1u) ? 0u : __float_as_uint(v);
                    if (key > k1)      { k2 = k1; c2 = c1; k1 = key; c1 = col; }
                    else if (key > k2) { k2 = key; c2 = col; }
                }
                unsigned m1 = __reduce_max_sync(FULL, k1);
                unsigned p1 = __reduce_min_sync(FULL, (k1 == m1) ? (unsigned)c1 : FULL);
                bool winner = (k1 == m1) && ((unsigned)c1 == p1);
                unsigned sk = winner ? k2 : k1;
                int      sc = winner ? c2 : c1;
                unsigned m2 = __reduce_max_sync(FULL, sk);
                unsigned p2 = __reduce_min_sync(FULL, (sk == m2) ? (unsigned)sc : FULL);
                if (lane == src) {
                    hkey[j2] = m1; hcol[j2] = (int)p1;
                    bkey[j2] = m2; bcol[j2] = (int)p2;
                }
            }
        }
    }

    __syncwarp();

    // ---------- fused output write: zeros + one-hot, coalesced float4 ----------
    #pragma unroll 1
    for (int row = 0; row < NN; row++) {
        int pc = s_perm[row];
        float4* op = (float4*)(obase + (size_t)row * NN);
        #pragma unroll
        for (int h = 0; h < 2; h++) {
            int f4 = lane + 32 * h;
            int c0 = 4 * f4;
            float4 vv;
            vv.x = (pc == c0 + 0) ? 1.0f : 0.0f;
            vv.y = (pc == c0 + 1) ? 1.0f : 0.0f;
            vv.z = (pc == c0 + 2) ? 1.0f : 0.0f;
            vv.w = (pc == c0 + 3) ? 1.0f : 0.0f;
            op[f4] = vv;
        }
    }
}

extern "C" void kernel_launch(void* const* d_in, const int* in_sizes, int n_in,
                              void* d_out, int out_size) {
    const float* soft = (const float*)d_in[0];
    float* out = (float*)d_out;
    greedy_perm_kernel<<<256, 32>>>(soft, out);
}

// round 4
// speedup vs baseline: 1.0404x; 1.0404x over previous
#include <cuda_runtime.h>
#include <cstdint>

// B=256 batches, N=256. Greedy masked argmax, one warp per batch, warp-synchronous.
// Lane owns rows j*32+lane (j=0..7): head (hkey = fp32 bits of max over unmasked
// cols; softmax values are in (0,1) so bits < 2^30, order-monotone; 0 = dead),
// backup (2nd best) in SMEM, phantom bitmask ph (stale head = upper bound).
// Selection: REDUX max over keys, REDUX min over packed (phantom<<16|row<<8|col)
// => exact reference tie-breaking (max value, then smallest flat index; real
// rows beat phantoms at equal key, which is safe since phantom true key < stale).
// NOTE: all state arrays are accessed with static indices only (no local-mem demotion).

#define NN 256
#define FULL 0xFFFFFFFFu

__global__ __launch_bounds__(32)
void greedy_perm_kernel(const float* __restrict__ scores, float* __restrict__ out) {
    __shared__ unsigned long long s_bak[NN];  // hi32 = key, lo8 = col; 0 = none
    __shared__ int s_perm[NN];

    const int b = blockIdx.x;
    const int lane = threadIdx.x;
    const float* base = scores + (size_t)b * NN * NN;
    float* obase = out + (size_t)b * NN * NN;

    unsigned hkey[8]; int hcol[8];
    unsigned cmask[8];
    unsigned ph = 0u;
    #pragma unroll
    for (int k = 0; k < 8; k++) cmask[k] = 0u;

    // ---------- init: lane scans its own 8 rows, local top-2, pipelined loads ----------
    #pragma unroll 1
    for (int j = 0; j < 8; j++) {
        const float4* rp = (const float4*)(base + (size_t)(j * 32 + lane) * NN);
        unsigned k1 = 0u, k2 = 0u; int c1 = 0, c2 = 0;
        float4 buf[4];
        #pragma unroll
        for (int q = 0; q < 4; q++) buf[q] = __ldg(rp + q);
        #pragma unroll 1
        for (int ch = 0; ch < 16; ch++) {
            float4 nxt[4];
            if (ch < 15) {
                #pragma unroll
                for (int q = 0; q < 4; q++) nxt[q] = __ldg(rp + (ch + 1) * 4 + q);
            }
            #pragma unroll
            for (int q = 0; q < 4; q++) {
                float v4[4] = {buf[q].x, buf[q].y, buf[q].z, buf[q].w};
                #pragma unroll
                for (int e = 0; e < 4; e++) {
                    unsigned key = __float_as_uint(v4[e]);
                    int col = ch * 16 + q * 4 + e;
                    if (key > k1)      { k2 = k1; c2 = c1; k1 = key; c1 = col; }
                    else if (key > k2) { k2 = key; c2 = col; }
                }
            }
            #pragma unroll
            for (int q = 0; q < 4; q++) buf[q] = nxt[q];
        }
        hkey[j] = k1; hcol[j] = c1;
        s_bak[j * 32 + lane] = ((unsigned long long)k2 << 32) | (unsigned)c2;
    }
    __syncwarp();

    // ---------- greedy loop ----------
    int accepted = 0;
    while (accepted < NN) {
        // local best over 8 owned slots (ascending row + strict > => smallest row on ties)
        unsigned bk = 0u, bp = 0x1FFFFu;
        #pragma unroll
        for (int j = 0; j < 8; j++) {
            unsigned pk = (((ph >> j) & 1u) << 16) |
                          (unsigned)((j * 32 + lane) << 8) | (unsigned)hcol[j];
            if (hkey[j] > bk) { bk = hkey[j]; bp = pk; }
        }
        unsigned m   = __reduce_max_sync(FULL, bk);
        unsigned sel = __reduce_min_sync(FULL, (bk == m) ? bp : FULL);
        int r    = (int)((sel >> 8) & 255u);
        int slot = r >> 5;
        int rl   = r & 31;

        if (sel & 0x10000u) {
            // phantom winner: cooperative masked top-2 rescan of row r
            const float* rp = base + (size_t)r * NN;
            unsigned k1 = 0u, k2 = 0u; int c1 = 0, c2 = 0;
            #pragma unroll
            for (int k = 0; k < 8; k++) {
                int col = k * 32 + lane;
                float v = __ldg(rp + col);
                unsigned key = ((cmask[k] >> lane) & 1u) ? 0u : __float_as_uint(v);
                if (key > k1)      { k2 = k1; c2 = c1; k1 = key; c1 = col; }
                else if (key > k2) { k2 = key; c2 = col; }
            }
            unsigned m1 = __reduce_max_sync(FULL, k1);
            unsigned p1 = __reduce_min_sync(FULL, (k1 == m1) ? (unsigned)c1 : FULL);
            bool win = (k1 == m1) && ((unsigned)c1 == p1);
            unsigned sk = win ? k2 : k1;
            int      sc = win ? c2 : c1;
            unsigned m2 = __reduce_max_sync(FULL, sk);
            unsigned p2 = __reduce_min_sync(FULL, (sk == m2) ? (unsigned)sc : FULL);
            if (lane == rl) {
                #pragma unroll
                for (int j = 0; j < 8; j++)
                    if (j == slot) { hkey[j] = m1; hcol[j] = (int)p1; }
                ph &= ~(1u << slot);
                s_bak[r] = ((unsigned long long)m2 << 32) | p2;
            }
            continue;  // redo selection with refreshed key
        }

        int c = (int)(sel & 255u);
        if (lane == 0) s_perm[r] = c;

        // mask col c (replicated, static indexing)
        {
            int w = c >> 5; unsigned bit = 1u << (c & 31);
            #pragma unroll
            for (int k = 0; k < 8; k++) if (k == w) cmask[k] |= bit;
        }
        // kill selected row's head
        if (lane == rl) {
            #pragma unroll
            for (int j = 0; j < 8; j++) if (j == slot) hkey[j] = 0u;
        }
        accepted++;
        if (accepted == NN) break;

        // head-hit handling: promote backup (validity checked lazily) or go phantom
        #pragma unroll
        for (int j = 0; j < 8; j++) {
            if (hkey[j] != 0u && !((ph >> j) & 1u) && hcol[j] == c) {
                unsigned long long bv = s_bak[j * 32 + lane];
                unsigned bkk = (unsigned)(bv >> 32);
                int bcc = (int)(bv & 255u);
                unsigned mb = 1u;
                int w2 = bcc >> 5;
                #pragma unroll
                for (int k = 0; k < 8; k++)
                    if (k == w2) mb = (cmask[k] >> (bcc & 31)) & 1u;
                if (bkk != 0u && mb == 0u) {
                    hkey[j] = bkk; hcol[j] = bcc;
                    s_bak[j * 32 + lane] = 0ull;
                } else {
                    ph |= 1u << j;
                }
            }
        }
    }

    __syncwarp();

    // ---------- fused output: zeros + one-hot, coalesced float4 ----------
    #pragma unroll 1
    for (int row = 0; row < NN; row++) {
        int pc = s_perm[row];  // broadcast LDS
        float4* op = (float4*)(obase + (size_t)row * NN);
        #pragma unroll
        for (int h = 0; h < 2; h++) {
            int f4 = lane + 32 * h;
            int c0 = 4 * f4;
            float4 vv;
            vv.x = (pc == c0 + 0) ? 1.0f : 0.0f;
            vv.y = (pc == c0 + 1) ? 1.0f : 0.0f;
            vv.z = (pc == c0 + 2) ? 1.0f : 0.0f;
            vv.w = (pc == c0 + 3) ? 1.0f : 0.0f;
            op[f4] = vv;
        }
    }
}

extern "C" void kernel_launch(void* const* d_in, const int* in_sizes, int n_in,
                              void* d_out, int out_size) {
    const float* soft = (const float*)d_in[0];
    float* out = (float*)d_out;
    greedy_perm_kernel<<<256, 32>>>(soft, out);
}

// round 5
// speedup vs baseline: 1.6009x; 1.5388x over previous
#include <cuda_runtime.h>
#include <cstdint>

// B=256, N=256. Greedy masked argmax, one warp per batch, warp-synchronous.
// Lane owns rows j*32+lane (j=0..7), all state in registers with STATIC indexing:
//   hkey/hcol : exact current argmax over unmasked cols (fp32 bits; softmax
//               values in (0,1) are order-monotone as uint32; 0 = dead)
//   bkey/bcol : exact 2nd best, eagerly invalidated when its col is masked
//               (so bkey!=0 => promotable exactly: masking only removes cols,
//               and nothing ranks between head and backup).
// Selection: REDUX max over keys, REDUX min over packed (row<<8|col) among
// attainers == smallest flat index => exact reference tie-breaking.

#define NN 256
#define FULL 0xFFFFFFFFu

// Warp-cooperative exact top-2 of one row. Lane holds cols 4*lane..4*lane+3
// (vec a) and 128+4*lane.. (vec bq). mwA/mwB are this lane's mask words.
__device__ __forceinline__ void top2_row(float4 a, float4 bq,
                                         unsigned mwA, unsigned mwB, int lane,
                                         unsigned& m1, unsigned& p1,
                                         unsigned& m2, unsigned& p2) {
    unsigned k1 = 0u, k2 = 0u; int c1 = 0, c2 = 0;
    const int bit0 = 4 * (lane & 7);
    float va[4] = {a.x, a.y, a.z, a.w};
    float vb[4] = {bq.x, bq.y, bq.z, bq.w};
    #pragma unroll
    for (int i = 0; i < 4; i++) {
        unsigned key = ((mwA >> (bit0 + i)) & 1u) ? 0u : __float_as_uint(va[i]);
        int col = 4 * lane + i;
        if (key > k1)      { k2 = k1; c2 = c1; k1 = key; c1 = col; }
        else if (key > k2) { k2 = key; c2 = col; }
    }
    #pragma unroll
    for (int i = 0; i < 4; i++) {
        unsigned key = ((mwB >> (bit0 + i)) & 1u) ? 0u : __float_as_uint(vb[i]);
        int col = 128 + 4 * lane + i;
        if (key > k1)      { k2 = k1; c2 = c1; k1 = key; c1 = col; }
        else if (key > k2) { k2 = key; c2 = col; }
    }
    m1 = __reduce_max_sync(FULL, k1);
    p1 = __reduce_min_sync(FULL, (k1 == m1) ? (unsigned)c1 : FULL);
    const bool win = (k1 == m1) && ((unsigned)c1 == p1);
    const unsigned sk = win ? k2 : k1;
    const unsigned sc = win ? (unsigned)c2 : (unsigned)c1;
    m2 = __reduce_max_sync(FULL, sk);
    p2 = __reduce_min_sync(FULL, (sk == m2) ? sc : FULL);
}

__global__ __launch_bounds__(32)
void greedy_perm_kernel(const float* __restrict__ scores, float* __restrict__ out) {
    __shared__ int s_perm[NN];

    const int b = blockIdx.x;
    const int lane = threadIdx.x;
    const float* base = scores + (size_t)b * NN * NN;
    float* obase = out + (size_t)b * NN * NN;

    unsigned hkey[8]; int hcol[8];
    unsigned bkey[8]; int bcol[8];
    unsigned cmask[8];
    #pragma unroll
    for (int k = 0; k < 8; k++) cmask[k] = 0u;

    // ---------- init: coalesced float4 loads, 4 rows batched (MLP), top-2 ----------
    #pragma unroll 1
    for (int rg = 0; rg < 64; rg++) {
        float4 A[4], Bq[4];
        #pragma unroll
        for (int q = 0; q < 4; q++) {
            const float4* rp = (const float4*)(base + (size_t)(rg * 4 + q) * NN);
            A[q]  = __ldg(rp + lane);
            Bq[q] = __ldg(rp + 32 + lane);
        }
        #pragma unroll
        for (int q = 0; q < 4; q++) {
            unsigned m1, p1, m2, p2;
            top2_row(A[q], Bq[q], 0u, 0u, lane, m1, p1, m2, p2);
            const int row = rg * 4 + q;
            if (lane == (row & 31)) {
                const int slot = row >> 5;
                #pragma unroll
                for (int j = 0; j < 8; j++)
                    if (j == slot) { hkey[j] = m1; hcol[j] = (int)p1;
                                     bkey[j] = m2; bcol[j] = (int)p2; }
            }
        }
    }

    // ---------- 256 sequential greedy steps ----------
    #pragma unroll 1
    for (int it = 0; it < NN; it++) {
        // local best over 8 owned rows (ascending row + strict > => smallest row on ties)
        unsigned bk = 0u, bp = FULL;
        #pragma unroll
        for (int j = 0; j < 8; j++) {
            if (hkey[j] > bk) {
                bk = hkey[j];
                bp = (unsigned)(((j * 32 + lane) << 8) | hcol[j]);
            }
        }
        const unsigned m   = __reduce_max_sync(FULL, bk);
        const unsigned sel = __reduce_min_sync(FULL, (bk == m) ? bp : FULL);
        const int r = (int)((sel >> 8) & 255u);
        const int c = (int)(sel & 255u);

        if (lane == 0) s_perm[r] = c;

        // mask col c (replicated, static indexing)
        {
            const int w = c >> 5; const unsigned bit = 1u << (c & 31);
            #pragma unroll
            for (int k = 0; k < 8; k++) if (k == w) cmask[k] |= bit;
        }
        // kill assigned row's head
        if (lane == (r & 31)) {
            const int slot = r >> 5;
            #pragma unroll
            for (int j = 0; j < 8; j++) if (j == slot) hkey[j] = 0u;
        }

        if (it == NN - 1) break;

        // eager backup invalidation + exact head promotion
        unsigned need = 0u;
        #pragma unroll
        for (int j = 0; j < 8; j++) {
            if (bcol[j] == c) bkey[j] = 0u;
            if (hkey[j] != 0u && hcol[j] == c) {
                if (bkey[j] != 0u) { hkey[j] = bkey[j]; hcol[j] = bcol[j]; bkey[j] = 0u; }
                else               need |= (1u << j);
            }
        }

        // rescans (rare): one combined ballot; cooperative top-2 refill
        unsigned lanes_need = __ballot_sync(FULL, need != 0u);
        while (lanes_need) {
            const int src = __ffs(lanes_need) - 1; lanes_need &= lanes_need - 1;
            unsigned em = __shfl_sync(FULL, need, src);
            while (em) {
                const int jd = __ffs(em) - 1; em &= em - 1;
                const int row = jd * 32 + src;
                const float4* rp = (const float4*)(base + (size_t)row * NN);
                const float4 a  = __ldg(rp + lane);
                const float4 bq = __ldg(rp + 32 + lane);
                unsigned mwA = 0u, mwB = 0u;
                #pragma unroll
                for (int k = 0; k < 4; k++)
                    if ((lane >> 3) == k) { mwA = cmask[k]; mwB = cmask[k + 4]; }
                unsigned m1, p1, m2, p2;
                top2_row(a, bq, mwA, mwB, lane, m1, p1, m2, p2);
                if (lane == src) {
                    #pragma unroll
                    for (int j = 0; j < 8; j++)
                        if (j == jd) { hkey[j] = m1; hcol[j] = (int)p1;
                                       bkey[j] = m2; bcol[j] = (int)p2; }
                }
            }
        }
    }

    __syncwarp();

    // ---------- fused output: zeros + one-hot, coalesced float4 ----------
    #pragma unroll 1
    for (int row = 0; row < NN; row++) {
        const int pc = s_perm[row];  // broadcast LDS
        float4* op = (float4*)(obase + (size_t)row * NN);
        #pragma unroll
        for (int h = 0; h < 2; h++) {
            const int f4 = lane + 32 * h;
            const int c0 = 4 * f4;
            float4 vv;
            vv.x = (pc == c0 + 0) ? 1.0f : 0.0f;
            vv.y = (pc == c0 + 1) ? 1.0f : 0.0f;
            vv.z = (pc == c0 + 2) ? 1.0f : 0.0f;
            vv.w = (pc == c0 + 3) ? 1.0f : 0.0f;
            op[f4] = vv;
        }
    }
}

extern "C" void kernel_launch(void* const* d_in, const int* in_sizes, int n_in,
                              void* d_out, int out_size) {
    const float* soft = (const float*)d_in[0];
    float* out = (float*)d_out;
    greedy_perm_kernel<<<256, 32>>>(soft, out);
}

// round 6
// speedup vs baseline: 2.2187x; 1.3859x over previous
#include <cuda_runtime.h>
#include <cstdint>

// B=256, N=256. Greedy masked argmax, one warp per batch, warp-synchronous.
// Keys = fp32 bit patterns (softmax values in (0,1) => positive, order-monotone
// as uint32; 0 = dead/masked). Lexicographic (max key, min flat index) via
// 64-bit local keys (key<<32 | ~pk) + 2 REDUX => exact reference tie-breaking.

#define NN 256
#define FULL 0xFFFFFFFFu
typedef unsigned long long u64;

__device__ __forceinline__ u64 pairmax(u64 a, u64 b) { return a > b ? a : b; }

__global__ __launch_bounds__(32)
void greedy_perm_kernel(const float* __restrict__ scores, float* __restrict__ out) {
    __shared__ u64 s_h[NN];    // init staging: (key<<32)|col
    __shared__ int s_perm[NN];

    const int b = blockIdx.x;
    const int lane = threadIdx.x;
    const float* base = scores + (size_t)b * NN * NN;
    float* obase = out + (size_t)b * NN * NN;

    unsigned hkey[8]; int hcol[8];
    unsigned cmask[8];
    #pragma unroll
    for (int k = 0; k < 8; k++) cmask[k] = 0u;

    // ---------- init: coalesced float4, 8 rows batched, top-1, 2 REDUX/row ----------
    #pragma unroll 1
    for (int rg = 0; rg < 32; rg++) {
        float4 A[8], Bq[8];
        #pragma unroll
        for (int q = 0; q < 8; q++) {
            const float4* rp = (const float4*)(base + (size_t)(rg * 8 + q) * NN);
            A[q]  = __ldg(rp + lane);
            Bq[q] = __ldg(rp + 32 + lane);
        }
        #pragma unroll
        for (int q = 0; q < 8; q++) {
            // lane holds cols 4*lane..+3 (A) and 128+4*lane..+3 (Bq)
            const int c0 = 4 * lane;
            u64 w[8];
            w[0] = ((u64)__float_as_uint(A[q].x)  << 32) | (unsigned)~(c0 + 0);
            w[1] = ((u64)__float_as_uint(A[q].y)  << 32) | (unsigned)~(c0 + 1);
            w[2] = ((u64)__float_as_uint(A[q].z)  << 32) | (unsigned)~(c0 + 2);
            w[3] = ((u64)__float_as_uint(A[q].w)  << 32) | (unsigned)~(c0 + 3);
            w[4] = ((u64)__float_as_uint(Bq[q].x) << 32) | (unsigned)~(128 + c0 + 0);
            w[5] = ((u64)__float_as_uint(Bq[q].y) << 32) | (unsigned)~(128 + c0 + 1);
            w[6] = ((u64)__float_as_uint(Bq[q].z) << 32) | (unsigned)~(128 + c0 + 2);
            w[7] = ((u64)__float_as_uint(Bq[q].w) << 32) | (unsigned)~(128 + c0 + 3);
            u64 loc = pairmax(pairmax(pairmax(w[0], w[1]), pairmax(w[2], w[3])),
                              pairmax(pairmax(w[4], w[5]), pairmax(w[6], w[7])));
            unsigned k1 = (unsigned)(loc >> 32);
            unsigned c1 = (~(unsigned)loc) & 255u;
            unsigned m1 = __reduce_max_sync(FULL, k1);
            unsigned p1 = __reduce_min_sync(FULL, (k1 == m1) ? c1 : FULL);
            if (lane == 0)
                s_h[rg * 8 + q] = ((u64)m1 << 32) | p1;
        }
    }
    __syncwarp();
    #pragma unroll
    for (int j = 0; j < 8; j++) {
        u64 hv = s_h[j * 32 + lane];
        hkey[j] = (unsigned)(hv >> 32);
        hcol[j] = (int)(hv & 255u);
    }

    const unsigned laneP = (unsigned)lane << 8;

    // ---------- 256 sequential greedy steps ----------
    #pragma unroll 1
    for (int it = 0; it < NN; it++) {
        // local lexicographic max over 8 owned rows: 3-level pairwise tree, no shuffles
        u64 t[8];
        #pragma unroll
        for (int j = 0; j < 8; j++) {
            unsigned pk = (unsigned)(j << 13) | laneP | (unsigned)hcol[j]; // (row<<8)|col
            t[j] = ((u64)hkey[j] << 32) | (u64)(unsigned)~pk;
        }
        u64 loc = pairmax(pairmax(pairmax(t[0], t[1]), pairmax(t[2], t[3])),
                          pairmax(pairmax(t[4], t[5]), pairmax(t[6], t[7])));
        unsigned bk = (unsigned)(loc >> 32);
        unsigned bp = ~(unsigned)loc;

        const unsigned m   = __reduce_max_sync(FULL, bk);
        const unsigned sel = __reduce_min_sync(FULL, (bk == m) ? bp : FULL);
        const int r = (int)((sel >> 8) & 255u);
        const int c = (int)(sel & 255u);

        if (lane == 0) s_perm[r] = c;

        // mask col c (replicated, static indexing)
        {
            const int w = c >> 5; const unsigned bit = 1u << (c & 31);
            #pragma unroll
            for (int k = 0; k < 8; k++) if (k == w) cmask[k] |= bit;
        }
        // kill assigned row's head
        if (lane == (r & 31)) {
            const int slot = r >> 5;
            #pragma unroll
            for (int j = 0; j < 8; j++) if (j == slot) hkey[j] = 0u;
        }

        if (it == NN - 1) break;

        // rows whose cached argmax col just got masked -> eager rescan
        unsigned need = 0u;
        #pragma unroll
        for (int j = 0; j < 8; j++)
            if (hkey[j] != 0u && hcol[j] == c) need |= (1u << j);

        unsigned ln = __ballot_sync(FULL, need != 0u);
        while (ln) {
            const int src = __ffs(ln) - 1; ln &= ln - 1;
            unsigned em = __shfl_sync(FULL, need, src);
            while (em) {
                const int jd = __ffs(em) - 1; em &= em - 1;
                const float* rp = base + (size_t)(jd * 32 + src) * NN;
                u64 w[8];
                #pragma unroll
                for (int k = 0; k < 8; k++) {
                    const float v = __ldg(rp + k * 32 + lane);
                    const unsigned key = ((cmask[k] >> lane) & 1u) ? 0u : __float_as_uint(v);
                    w[k] = ((u64)key << 32) | (u64)(unsigned)~(unsigned)(k * 32 + lane);
                }
                u64 lq = pairmax(pairmax(pairmax(w[0], w[1]), pairmax(w[2], w[3])),
                                 pairmax(pairmax(w[4], w[5]), pairmax(w[6], w[7])));
                const unsigned kk = (unsigned)(lq >> 32);
                const unsigned cc = (~(unsigned)lq) & 255u;
                const unsigned mm = __reduce_max_sync(FULL, kk);
                const unsigned pc = __reduce_min_sync(FULL, (kk == mm) ? cc : FULL);
                if (lane == src) {
                    #pragma unroll
                    for (int j = 0; j < 8; j++)
                        if (j == jd) { hkey[j] = mm; hcol[j] = (int)pc; }
                }
            }
        }
    }

    __syncwarp();

    // ---------- fused output: zeros + one-hot, coalesced float4 ----------
    #pragma unroll 4
    for (int row = 0; row < NN; row++) {
        const int pc = s_perm[row];  // broadcast LDS
        float4* op = (float4*)(obase + (size_t)row * NN);
        #pragma unroll
        for (int h = 0; h < 2; h++) {
            const int f4 = lane + 32 * h;
            const int c0 = 4 * f4;
            float4 vv;
            vv.x = (pc == c0 + 0) ? 1.0f : 0.0f;
            vv.y = (pc == c0 + 1) ? 1.0f : 0.0f;
            vv.z = (pc == c0 + 2) ? 1.0f : 0.0f;
            vv.w = (pc == c0 + 3) ? 1.0f : 0.0f;
            op[f4] = vv;
        }
    }
}

extern "C" void kernel_launch(void* const* d_in, const int* in_sizes, int n_in,
                              void* d_out, int out_size) {
    const float* soft = (const float*)d_in[0];
    float* out = (float*)d_out;
    greedy_perm_kernel<<<256, 32>>>(soft, out);
}